// round 1
// baseline (speedup 1.0000x reference)
#include <cuda_runtime.h>
#include <cstdint>

// ROIClassifierHead: out = relu(relu(X@W1+b1)@W2+b2)@Wc+bc
// X = features reshaped [2048, 12544]; batch_indices is an identity permutation -> ignored.
//
// TF32 mma.sync GEMM, 128x128x32 block tile, 8 warps (2x4), 64x32 warp tile,
// cp.async double buffering, padded smem (A stride 36, B stride 136 -> bank-conflict-free
// fragment reads). Inputs rounded to tf32 with cvt.rna (unbiased) for rel_err ~4e-4.

#define BM 128
#define BN 128
#define BK 32
#define ASTRIDE 36   // 32 + 4 pad: frag read bank = (4g + t) % 32 -> conflict free
#define BSTRIDE 136  // 128 + 8 pad: frag read bank = (8t + g) % 32 -> conflict free

#define M_TOTAL 2048
#define HID 1024
#define FEAT 12544
#define NCLS 81

// scratch activations (device globals: no allocation allowed)
__device__ float g_C1[M_TOTAL * HID];
__device__ float g_C2[M_TOTAL * HID];

__device__ __forceinline__ unsigned f2tf(float x) {
    unsigned r;
    asm("cvt.rna.tf32.f32 %0, %1;" : "=r"(r) : "f"(x));
    return r;
}

__device__ __forceinline__ void mma8(float* c, const unsigned* a, const unsigned* b) {
    asm volatile(
        "mma.sync.aligned.m16n8k8.row.col.f32.tf32.tf32.f32 "
        "{%0,%1,%2,%3},{%4,%5,%6,%7},{%8,%9},{%0,%1,%2,%3};"
        : "+f"(c[0]), "+f"(c[1]), "+f"(c[2]), "+f"(c[3])
        : "r"(a[0]), "r"(a[1]), "r"(a[2]), "r"(a[3]), "r"(b[0]), "r"(b[1]));
}

__device__ __forceinline__ void cp16(uint32_t dst, const void* src) {
    asm volatile("cp.async.cg.shared.global [%0], [%1], 16;" ::"r"(dst), "l"(src));
}
__device__ __forceinline__ void cp4z(uint32_t dst, const void* src, int srcsize) {
    // 4-byte copy with zero-fill when srcsize==0 (for N=81 edge)
    asm volatile("cp.async.ca.shared.global [%0], [%1], 4, %2;" ::"r"(dst), "l"(src), "r"(srcsize));
}
__device__ __forceinline__ void cp_commit() { asm volatile("cp.async.commit_group;"); }
__device__ __forceinline__ void cp_wait1() { asm volatile("cp.async.wait_group 1;" ::: "memory"); }
__device__ __forceinline__ void cp_wait0() { asm volatile("cp.async.wait_group 0;" ::: "memory"); }

// A: [M, K] row-major (ldA), B: [K, Ncols] row-major (ldB), C: [M, ldC]
// Grid: (ceil(Ncols/BN), M/BM), 256 threads.
template <bool BVEC, bool RELU>
__global__ __launch_bounds__(256) void gemm_tf32_kernel(
    const float* __restrict__ A, const float* __restrict__ B,
    const float* __restrict__ bias, float* __restrict__ C,
    int Ncols, int K, int ldA, int ldB, int ldC)
{
    extern __shared__ float sm[];
    float* As = sm;                         // [2][BM][ASTRIDE]
    float* Bs = sm + 2 * BM * ASTRIDE;      // [2][BK][BSTRIDE]

    const int tid  = threadIdx.x;
    const int lane = tid & 31;
    const int warp = tid >> 5;
    const int wm = (warp >> 2) * 64;        // 0 / 64
    const int wn = (warp & 3) * 32;         // 0/32/64/96
    const int g = lane >> 2;                // 0..7
    const int t = lane & 3;                 // 0..3
    const int bm = blockIdx.y * BM;
    const int bn = blockIdx.x * BN;

    const uint32_t sA = (uint32_t)__cvta_generic_to_shared(As);
    const uint32_t sB = (uint32_t)__cvta_generic_to_shared(Bs);

    const int KT = K / BK;

    float acc[4][4][4];
#pragma unroll
    for (int mt = 0; mt < 4; mt++)
#pragma unroll
        for (int nt = 0; nt < 4; nt++)
#pragma unroll
            for (int i = 0; i < 4; i++) acc[mt][nt][i] = 0.0f;

    auto loadA = [&](int kt, int buf) {
#pragma unroll
        for (int i = 0; i < 4; i++) {
            int fid = tid + i * 256;
            int row = fid >> 3;
            int c4  = (fid & 7) << 2;
            const float* src = A + (size_t)(bm + row) * ldA + kt * BK + c4;
            uint32_t dst = sA + (uint32_t)(((buf * BM + row) * ASTRIDE + c4) * 4);
            cp16(dst, src);
        }
    };
    auto loadB = [&](int kt, int buf) {
        if (BVEC) {
#pragma unroll
            for (int i = 0; i < 4; i++) {
                int fid = tid + i * 256;
                int row = fid >> 5;
                int c4  = (fid & 31) << 2;
                const float* src = B + (size_t)(kt * BK + row) * ldB + bn + c4;
                uint32_t dst = sB + (uint32_t)(((buf * BK + row) * BSTRIDE + c4) * 4);
                cp16(dst, src);
            }
        } else {
#pragma unroll
            for (int i = 0; i < 16; i++) {
                int fid = tid + i * 256;
                int row = fid >> 7;
                int c   = fid & 127;
                int col = bn + c;
                int ss  = (col < Ncols) ? 4 : 0;
                const float* src = B + (size_t)(kt * BK + row) * ldB + (col < Ncols ? col : 0);
                uint32_t dst = sB + (uint32_t)(((buf * BK + row) * BSTRIDE + c) * 4);
                cp4z(dst, src, ss);
            }
        }
    };

    loadA(0, 0);
    loadB(0, 0);
    cp_commit();

    int buf = 0;
    for (int kt = 0; kt < KT; kt++) {
        if (kt + 1 < KT) {
            loadA(kt + 1, buf ^ 1);
            loadB(kt + 1, buf ^ 1);
            cp_commit();
            cp_wait1();
        } else {
            cp_wait0();
        }
        __syncthreads();

        const float* Ab = As + buf * BM * ASTRIDE;
        const float* Bb = Bs + buf * BK * BSTRIDE;

#pragma unroll
        for (int ks = 0; ks < 4; ks++) {
            unsigned af[4][4];
            unsigned bf[4][2];
#pragma unroll
            for (int mt = 0; mt < 4; mt++) {
                int r  = wm + mt * 16 + g;
                int cA = ks * 8 + t;
                af[mt][0] = f2tf(Ab[r * ASTRIDE + cA]);
                af[mt][1] = f2tf(Ab[(r + 8) * ASTRIDE + cA]);
                af[mt][2] = f2tf(Ab[r * ASTRIDE + cA + 4]);
                af[mt][3] = f2tf(Ab[(r + 8) * ASTRIDE + cA + 4]);
            }
#pragma unroll
            for (int nt = 0; nt < 4; nt++) {
                int cB = wn + nt * 8 + g;
                int rB = ks * 8 + t;
                bf[nt][0] = f2tf(Bb[rB * BSTRIDE + cB]);
                bf[nt][1] = f2tf(Bb[(rB + 4) * BSTRIDE + cB]);
            }
#pragma unroll
            for (int mt = 0; mt < 4; mt++)
#pragma unroll
                for (int nt = 0; nt < 4; nt++) mma8(acc[mt][nt], af[mt], bf[nt]);
        }
        __syncthreads();
        buf ^= 1;
    }

    // epilogue: bias (+ optional relu), guarded scalar stores (handles Ncols=81)
#pragma unroll
    for (int mt = 0; mt < 4; mt++) {
        int row0 = bm + wm + mt * 16 + g;
        int row1 = row0 + 8;
#pragma unroll
        for (int nt = 0; nt < 4; nt++) {
            int col = bn + wn + nt * 8 + 2 * t;
            float b0 = (col < Ncols) ? bias[col] : 0.0f;
            float b1 = (col + 1 < Ncols) ? bias[col + 1] : 0.0f;
            float v0 = acc[mt][nt][0] + b0;
            float v1 = acc[mt][nt][1] + b1;
            float v2 = acc[mt][nt][2] + b0;
            float v3 = acc[mt][nt][3] + b1;
            if (RELU) {
                v0 = fmaxf(v0, 0.0f);
                v1 = fmaxf(v1, 0.0f);
                v2 = fmaxf(v2, 0.0f);
                v3 = fmaxf(v3, 0.0f);
            }
            if (col < Ncols) {
                C[(size_t)row0 * ldC + col] = v0;
                C[(size_t)row1 * ldC + col] = v2;
            }
            if (col + 1 < Ncols) {
                C[(size_t)row0 * ldC + col + 1] = v1;
                C[(size_t)row1 * ldC + col + 1] = v3;
            }
        }
    }
}

extern "C" void kernel_launch(void* const* d_in, const int* in_sizes, int n_in,
                              void* d_out, int out_size)
{
    const float* feat = (const float*)d_in[0];   // [2048, 7,7,256] = [2048, 12544]
    // d_in[1] = batch_indices (identity permutation -> unused)
    const float* W1 = (const float*)d_in[2];     // [12544, 1024]
    const float* b1 = (const float*)d_in[3];
    const float* W2 = (const float*)d_in[4];     // [1024, 1024]
    const float* b2 = (const float*)d_in[5];
    const float* Wc = (const float*)d_in[6];     // [1024, 81]
    const float* bc = (const float*)d_in[7];
    float* out = (float*)d_out;                  // [2048, 81]

    float *C1, *C2;
    cudaGetSymbolAddress((void**)&C1, g_C1);
    cudaGetSymbolAddress((void**)&C2, g_C2);

    const size_t smem = (size_t)(2 * BM * ASTRIDE + 2 * BK * BSTRIDE) * sizeof(float); // 71680 B

    cudaFuncSetAttribute(gemm_tf32_kernel<true, true>,
                         cudaFuncAttributeMaxDynamicSharedMemorySize, (int)smem);
    cudaFuncSetAttribute(gemm_tf32_kernel<false, false>,
                         cudaFuncAttributeMaxDynamicSharedMemorySize, (int)smem);

    // layer 1: C1 = relu(X @ W1 + b1)   [2048,12544]x[12544,1024]
    gemm_tf32_kernel<true, true><<<dim3(HID / BN, M_TOTAL / BM), 256, smem>>>(
        feat, W1, b1, C1, HID, FEAT, FEAT, HID, HID);

    // layer 2: C2 = relu(C1 @ W2 + b2)  [2048,1024]x[1024,1024]
    gemm_tf32_kernel<true, true><<<dim3(HID / BN, M_TOTAL / BM), 256, smem>>>(
        C1, W2, b2, C2, HID, HID, HID, HID, HID);

    // layer 3: out = C2 @ Wc + bc       [2048,1024]x[1024,81]
    gemm_tf32_kernel<false, false><<<dim3(1, M_TOTAL / BM), 256, smem>>>(
        C2, Wc, bc, out, NCLS, HID, HID, NCLS, NCLS);
}

// round 6
// speedup vs baseline: 2.8496x; 2.8496x over previous
#include <cuda_runtime.h>
#include <cuda_fp16.h>
#include <cstdint>

// ROIClassifierHead: out = relu(relu(X@W1+b1)@W2+b2)@Wc+bc, X=[2048,12544] fp32.
// batch_indices is an identity permutation -> ignored.
//
// Legacy tensor path (virtual arch is compute_103: tcgen05 PTX is rejected by ptxas,
// so mma.sync is the only tensor route). fp16 m16n8k16 HMMA, ldmatrix fragments,
// SW128-xor swizzled smem, 3-stage cp.async pipeline, 128x64 CTA tile, 2 CTAs/SM.

#define M_TOTAL 2048
#define HID 1024
#define FEAT 12544
#define NCLS 81

#define BM 128
#define BN 64
#define BK 64                    // fp16 -> 128B rows
#define STAGES 3
#define A_BYTES (BM * 128)       // 16384
#define B_BYTES (BN * 128)       // 8192
#define STAGE_BYTES (A_BYTES + B_BYTES)

// ---------------- device scratch (no allocation allowed) ----------------
__device__ __half g_Xh[M_TOTAL * FEAT];      // X fp16 [2048, 12544]
__device__ __half g_W1T[HID * FEAT];         // W1^T fp16 [1024, 12544]  (K-major)
__device__ __half g_W2T[HID * HID];          // W2^T fp16 [1024, 1024]
__device__ __half g_WcT[128 * HID];          // Wc^T fp16 padded [128, 1024]
__device__ __half g_C1[M_TOTAL * HID];
__device__ __half g_C2[M_TOTAL * HID];

// ---------------- PTX helpers ----------------
__device__ __forceinline__ void cp16(uint32_t dst, const void* src) {
    asm volatile("cp.async.cg.shared.global [%0], [%1], 16;" ::"r"(dst), "l"(src));
}
__device__ __forceinline__ void cp_commit() { asm volatile("cp.async.commit_group;"); }
__device__ __forceinline__ void cp_wait1() { asm volatile("cp.async.wait_group 1;" ::: "memory"); }
__device__ __forceinline__ void cp_wait0() { asm volatile("cp.async.wait_group 0;" ::: "memory"); }

__device__ __forceinline__ void ldsm4(uint32_t& r0, uint32_t& r1, uint32_t& r2, uint32_t& r3,
                                      uint32_t addr) {
    asm volatile("ldmatrix.sync.aligned.m8n8.x4.shared.b16 {%0,%1,%2,%3}, [%4];"
                 : "=r"(r0), "=r"(r1), "=r"(r2), "=r"(r3) : "r"(addr));
}
__device__ __forceinline__ void mma16816(float* c, const uint32_t* a, uint32_t b0, uint32_t b1) {
    asm volatile(
        "mma.sync.aligned.m16n8k16.row.col.f32.f16.f16.f32 "
        "{%0,%1,%2,%3},{%4,%5,%6,%7},{%8,%9},{%0,%1,%2,%3};"
        : "+f"(c[0]), "+f"(c[1]), "+f"(c[2]), "+f"(c[3])
        : "r"(a[0]), "r"(a[1]), "r"(a[2]), "r"(a[3]), "r"(b0), "r"(b1));
}

// ---------------- pre-pass kernels ----------------
__global__ void cvt_f32_f16_kernel(const float4* __restrict__ in, uint2* __restrict__ out, int n4) {
    for (int i = blockIdx.x * blockDim.x + threadIdx.x; i < n4; i += gridDim.x * blockDim.x) {
        float4 v = in[i];
        __half2 a = __floats2half2_rn(v.x, v.y);
        __half2 b = __floats2half2_rn(v.z, v.w);
        uint2 o;
        o.x = *(unsigned*)&a;
        o.y = *(unsigned*)&b;
        out[i] = o;
    }
}

// in: [R, Cin] f32 row-major -> out: [Cout, R] f16 (zero-pad col >= Cin).
__global__ void transpose_cvt_kernel(const float* __restrict__ in, __half* __restrict__ out,
                                     int R, int Cin, int Cout) {
    __shared__ float t[32][33];
    int r0 = blockIdx.x * 32, c0 = blockIdx.y * 32;
    int tx = threadIdx.x, ty = threadIdx.y;
#pragma unroll
    for (int j = 0; j < 4; j++) {
        int row = r0 + ty + j * 8, col = c0 + tx;
        t[ty + j * 8][tx] = (col < Cin) ? in[(size_t)row * Cin + col] : 0.0f;
    }
    __syncthreads();
#pragma unroll
    for (int j = 0; j < 4; j++) {
        int oc = c0 + ty + j * 8;  // output row (N index)
        out[(size_t)oc * R + r0 + tx] = __float2half_rn(t[tx][ty + j * 8]);
    }
}

// ---------------- fp16 mma.sync GEMM ----------------
// C[M,Ncols] = A[M,K] * B[Nrows,K]^T (+bias, opt relu). A,B fp16 K-major.
// CTA tile 128x64, BK=64, 256 threads (8 warps: 4 in M x 2 in N, 32x32 warp tile).
template <bool F16OUT, bool RELU>
__global__ __launch_bounds__(256, 2) void gemm_f16_kernel(
    const __half* __restrict__ A, const __half* __restrict__ B,
    const float* __restrict__ bias, void* __restrict__ Cout,
    int K, int ldC, int Ncols)
{
    extern __shared__ char smem[];
    const uint32_t sb = (uint32_t)__cvta_generic_to_shared(smem);

    const int tid = threadIdx.x;
    const int lane = tid & 31;
    const int wid = tid >> 5;
    const int wm = (wid & 3) * 32;   // warp M offset in tile
    const int wn = (wid >> 2) * 32;  // warp N offset in tile
    const int bm = blockIdx.y * BM;
    const int bn = blockIdx.x * BN;
    const int KT = K / BK;

    // cp.async loader: 16B chunks, SW128 xor swizzle (chunk ^= row&7)
    const int lrow = tid >> 3;        // 0..31
    const int lc = tid & 7;           // 16B chunk in row
    auto load_stage = [&](int kt, int s) {
        uint32_t base = sb + s * STAGE_BYTES;
        const __half* Ag = A + (size_t)(bm + lrow) * K + kt * BK + lc * 8;
#pragma unroll
        for (int i = 0; i < 4; i++) {   // A: 128 rows
            int row = lrow + i * 32;
            uint32_t dst = base + row * 128 + ((lc ^ (row & 7)) << 4);
            cp16(dst, Ag + (size_t)i * 32 * K);
        }
        const __half* Bg = B + (size_t)(bn + lrow) * K + kt * BK + lc * 8;
#pragma unroll
        for (int i = 0; i < 2; i++) {   // B: 64 rows
            int row = lrow + i * 32;
            uint32_t dst = base + A_BYTES + row * 128 + ((lc ^ (row & 7)) << 4);
            cp16(dst, Bg + (size_t)i * 32 * K);
        }
    };

    float acc[2][4][4];
#pragma unroll
    for (int mt = 0; mt < 2; mt++)
#pragma unroll
        for (int nt = 0; nt < 4; nt++)
#pragma unroll
            for (int i = 0; i < 4; i++) acc[mt][nt][i] = 0.0f;

    load_stage(0, 0); cp_commit();
    load_stage(1, 1); cp_commit();

    // ldmatrix lane addressing (precompute row/chunk components)
    const int l15 = lane & 15;
    const int lhi = lane >> 4;        // k-chunk select within k16

    for (int kt = 0; kt < KT; kt++) {
        cp_wait1();
        __syncthreads();
        if (kt + 2 < KT) { load_stage(kt + 2, (kt + 2) % STAGES); cp_commit(); }

        uint32_t Ab = sb + (kt % STAGES) * STAGE_BYTES;
        uint32_t Bb = Ab + A_BYTES;

#pragma unroll
        for (int ks = 0; ks < 4; ks++) {
            uint32_t a[2][4], b[2][4];
#pragma unroll
            for (int mt = 0; mt < 2; mt++) {
                int row = wm + mt * 16 + l15;
                int kc = ks * 2 + lhi;
                ldsm4(a[mt][0], a[mt][1], a[mt][2], a[mt][3],
                      Ab + row * 128 + ((kc ^ (row & 7)) << 4));
            }
#pragma unroll
            for (int nt = 0; nt < 2; nt++) {
                int row = wn + nt * 16 + l15;
                int kc = ks * 2 + lhi;
                ldsm4(b[nt][0], b[nt][1], b[nt][2], b[nt][3],
                      Bb + row * 128 + ((kc ^ (row & 7)) << 4));
            }
#pragma unroll
            for (int mt = 0; mt < 2; mt++)
#pragma unroll
                for (int n8 = 0; n8 < 4; n8++) {
                    int g = n8 >> 1, s = n8 & 1;
                    mma16816(acc[mt][n8], a[mt], b[g][s], b[g][s + 2]);
                }
        }
        __syncthreads();
    }
    cp_wait0();

    // epilogue: thread (g = lane>>2, t = lane&3): rows g, g+8; cols 2t, 2t+1 per n8
    const int g = lane >> 2, t = lane & 3;
#pragma unroll
    for (int mt = 0; mt < 2; mt++) {
        int row0 = bm + wm + mt * 16 + g;
        int row1 = row0 + 8;
#pragma unroll
        for (int n8 = 0; n8 < 4; n8++) {
            int col = bn + wn + n8 * 8 + 2 * t;
            if (F16OUT) {
                float b0 = bias[col], b1 = bias[col + 1];
                float v0 = acc[mt][n8][0] + b0, v1 = acc[mt][n8][1] + b1;
                float v2 = acc[mt][n8][2] + b0, v3 = acc[mt][n8][3] + b1;
                if (RELU) {
                    v0 = fmaxf(v0, 0.f); v1 = fmaxf(v1, 0.f);
                    v2 = fmaxf(v2, 0.f); v3 = fmaxf(v3, 0.f);
                }
                __half* C = (__half*)Cout;
                *(__half2*)(C + (size_t)row0 * ldC + col) = __floats2half2_rn(v0, v1);
                *(__half2*)(C + (size_t)row1 * ldC + col) = __floats2half2_rn(v2, v3);
            } else {
                float b0 = (col < Ncols) ? bias[col] : 0.f;
                float b1 = (col + 1 < Ncols) ? bias[col + 1] : 0.f;
                float v0 = acc[mt][n8][0] + b0, v1 = acc[mt][n8][1] + b1;
                float v2 = acc[mt][n8][2] + b0, v3 = acc[mt][n8][3] + b1;
                if (RELU) {
                    v0 = fmaxf(v0, 0.f); v1 = fmaxf(v1, 0.f);
                    v2 = fmaxf(v2, 0.f); v3 = fmaxf(v3, 0.f);
                }
                float* C = (float*)Cout;
                if (col < Ncols) {
                    C[(size_t)row0 * ldC + col] = v0;
                    C[(size_t)row1 * ldC + col] = v2;
                }
                if (col + 1 < Ncols) {
                    C[(size_t)row0 * ldC + col + 1] = v1;
                    C[(size_t)row1 * ldC + col + 1] = v3;
                }
            }
        }
    }
}

// ---------------- host ----------------
extern "C" void kernel_launch(void* const* d_in, const int* in_sizes, int n_in,
                              void* d_out, int out_size)
{
    const float* feat = (const float*)d_in[0];
    const float* W1 = (const float*)d_in[2];
    const float* b1 = (const float*)d_in[3];
    const float* W2 = (const float*)d_in[4];
    const float* b2 = (const float*)d_in[5];
    const float* Wc = (const float*)d_in[6];
    const float* bc = (const float*)d_in[7];
    float* out = (float*)d_out;

    void *Xh, *W1T, *W2T, *WcT, *C1, *C2;
    cudaGetSymbolAddress(&Xh, g_Xh);
    cudaGetSymbolAddress(&W1T, g_W1T);
    cudaGetSymbolAddress(&W2T, g_W2T);
    cudaGetSymbolAddress(&WcT, g_WcT);
    cudaGetSymbolAddress(&C1, g_C1);
    cudaGetSymbolAddress(&C2, g_C2);

    const int smem = STAGES * STAGE_BYTES;  // 73728
    cudaFuncSetAttribute(gemm_f16_kernel<true, true>,
                         cudaFuncAttributeMaxDynamicSharedMemorySize, smem);
    cudaFuncSetAttribute(gemm_f16_kernel<false, false>,
                         cudaFuncAttributeMaxDynamicSharedMemorySize, smem);

    // pre-pass: X -> fp16, weights -> transposed fp16 (K-major)
    cvt_f32_f16_kernel<<<4096, 256>>>((const float4*)feat, (uint2*)Xh, M_TOTAL * FEAT / 4);
    transpose_cvt_kernel<<<dim3(FEAT / 32, HID / 32), dim3(32, 8)>>>(W1, (__half*)W1T, FEAT, HID, HID);
    transpose_cvt_kernel<<<dim3(HID / 32, HID / 32), dim3(32, 8)>>>(W2, (__half*)W2T, HID, HID, HID);
    transpose_cvt_kernel<<<dim3(HID / 32, 128 / 32), dim3(32, 8)>>>(Wc, (__half*)WcT, HID, NCLS, 128);

    // L1: C1 = relu(X @ W1 + b1)   grid 16x16 = 256 CTAs
    gemm_f16_kernel<true, true><<<dim3(HID / BN, M_TOTAL / BM), 256, smem>>>(
        (const __half*)Xh, (const __half*)W1T, b1, C1, FEAT, HID, HID);
    // L2: C2 = relu(C1 @ W2 + b2)
    gemm_f16_kernel<true, true><<<dim3(HID / BN, M_TOTAL / BM), 256, smem>>>(
        (const __half*)C1, (const __half*)W2T, b2, C2, HID, HID, HID);
    // L3: out = C2 @ Wc + bc  (fp32 out, Ncols=81, WcT padded to 128 rows)
    gemm_f16_kernel<false, false><<<dim3(128 / BN, M_TOTAL / BM), 256, smem>>>(
        (const __half*)C2, (const __half*)WcT, bc, out, HID, NCLS, NCLS);
}